// round 5
// baseline (speedup 1.0000x reference)
#include <cuda_runtime.h>
#include <cuda_bf16.h>
#include <cuda_fp8.h>
#include <cstdint>

#define BDIM 4096
#define DDIM 1024
#define BM 128
#define BN 256
#define BK 128              /* fp8 elements per k-tile (128 bytes/row) */
#define KTILES 8            /* 1024 / 128 */
#define MT 32               /* 4096 / 128 */
#define NT 16               /* 4096 / 256 */
#define STAGES 4
#define A_STAGE_BYTES 16384 /* 128 rows x 128B */
#define B_STAGE_BYTES 32768 /* 256 rows x 128B */
#define STAGE_BYTES (A_STAGE_BYTES + B_STAGE_BYTES)
#define TILE0 3072
#define GEMM_SMEM (TILE0 + STAGES * STAGE_BYTES) /* 199680 */
#define PSCALE 256.0f
#define INV_PSCALE 0.00390625f

// ---- scratch (static device globals; no runtime allocation) ----
__device__ float g_pe[BDIM];
__device__ float g_c[BDIM];
__device__ float g_kldiv[BDIM];
// tiled + swizzled fp8 operand storage, written by prep:
//  A: [mTile(32)][kTile(8)] tiles of 128 rows x 128 bytes (e4m3 centered log q)
//  B: [nTile(16)][kTile(8)] tiles of 256 rows x 128 bytes (e4m3 p*256)
__device__ __align__(1024) uint32_t g_aT[(size_t)BDIM * DDIM / 4];
__device__ __align__(1024) uint32_t g_bT[(size_t)BDIM * DDIM / 4];
__device__ float g_partLab[(size_t)NT * BDIM];
__device__ float g_partAll[(size_t)NT * BDIM];
__device__ float g_rowsum[16];
__device__ int g_cnt;

// ============================================================
// PTX helpers (non-"a" features only: mbarrier, bulk copy, mma.sync)
// ============================================================
__device__ __forceinline__ void mbar_init(uint32_t mbar, uint32_t cnt) {
    asm volatile("mbarrier.init.shared.b64 [%0], %1;" ::"r"(mbar), "r"(cnt) : "memory");
}
__device__ __forceinline__ void mbar_expect_tx(uint32_t mbar, uint32_t bytes) {
    asm volatile("mbarrier.arrive.expect_tx.shared.b64 _, [%0], %1;" ::"r"(mbar), "r"(bytes)
                 : "memory");
}
__device__ __forceinline__ void mbar_arrive(uint32_t mbar) {
    asm volatile("mbarrier.arrive.shared.b64 _, [%0];" ::"r"(mbar) : "memory");
}
__device__ __forceinline__ void mbar_wait(uint32_t mbar, uint32_t parity) {
    uint32_t done;
    asm volatile(
        "{\n\t.reg .pred p;\n\t"
        "mbarrier.try_wait.parity.acquire.cta.shared::cta.b64 p, [%1], %2;\n\t"
        "selp.b32 %0, 1, 0, p;\n\t}"
        : "=r"(done)
        : "r"(mbar), "r"(parity)
        : "memory");
    if (!done) {
        asm volatile(
            "{\n\t.reg .pred P1;\n\t"
            "WAIT_LOOP_%=:\n\t"
            "mbarrier.try_wait.parity.acquire.cta.shared::cta.b64 P1, [%0], %1, 0x989680;\n\t"
            "@P1 bra.uni WAIT_DONE_%=;\n\t"
            "bra.uni WAIT_LOOP_%=;\n\t"
            "WAIT_DONE_%=:\n\t}" ::"r"(mbar),
            "r"(parity)
            : "memory");
    }
}
__device__ __forceinline__ void bulk_g2s(uint32_t dst, const void* src, uint32_t bytes,
                                         uint32_t mbar) {
    asm volatile(
        "cp.async.bulk.shared::cluster.global.mbarrier::complete_tx::bytes [%0], [%1], %2, [%3];"
        ::"r"(dst), "l"(src), "r"(bytes), "r"(mbar)
        : "memory");
}
// fp8 e4m3 MMA: m16n8k32, fragment register shapes identical to bf16 m16n8k16
__device__ __forceinline__ void mma16832(float* d, const uint32_t* a, const uint32_t* b) {
    asm volatile(
        "mma.sync.aligned.m16n8k32.row.col.f32.e4m3.e4m3.f32 "
        "{%0,%1,%2,%3}, {%4,%5,%6,%7}, {%8,%9}, {%0,%1,%2,%3};\n"
        : "+f"(d[0]), "+f"(d[1]), "+f"(d[2]), "+f"(d[3])
        : "r"(a[0]), "r"(a[1]), "r"(a[2]), "r"(a[3]), "r"(b[0]), "r"(b[1]));
}
__device__ __forceinline__ void ldm4(uint32_t& r0, uint32_t& r1, uint32_t& r2, uint32_t& r3,
                                     uint32_t addr) {
    asm volatile("ldmatrix.sync.aligned.m8n8.x4.shared.b16 {%0,%1,%2,%3}, [%4];\n"
                 : "=r"(r0), "=r"(r1), "=r"(r2), "=r"(r3)
                 : "r"(addr));
}
// swizzled smem byte offset inside one [rows x 128B] tile (atom=16B, 8 atoms/row):
__device__ __forceinline__ uint32_t swz(int row, int atom) {
    return (uint32_t)(row * 128 + ((atom ^ (row & 7)) << 4));
}

// ============================================================
// Kernel 1: per-row preprocess + tiled/swizzled fp8 operand store
//   pe[i] = sum p log p ; c[i] = mean log q ; kldiv[i] = mean p(lp-lq)
//   A tiles: e4m3(log q - c)   B tiles: e4m3(p * 256)
// ============================================================
__global__ void __launch_bounds__(256) prep_kernel(const float* __restrict__ q,
                                                   const float* __restrict__ p) {
    const int r = blockIdx.x;
    const int t = threadIdx.x;
    const int lane = t & 31, w = t >> 5;

    float4 q4 = ((const float4*)(q + (size_t)r * DDIM))[t];
    float4 p4 = ((const float4*)(p + (size_t)r * DDIM))[t];
    float lq[4] = {logf(q4.x), logf(q4.y), logf(q4.z), logf(q4.w)};
    float lp[4] = {logf(p4.x), logf(p4.y), logf(p4.z), logf(p4.w)};
    float pv[4] = {p4.x, p4.y, p4.z, p4.w};

    float s_lq = (lq[0] + lq[1]) + (lq[2] + lq[3]);
    float s_plp = 0.f, s_kl = 0.f;
#pragma unroll
    for (int i = 0; i < 4; i++) {
        s_plp += pv[i] * lp[i];
        s_kl += pv[i] * (lp[i] - lq[i]);
    }
#pragma unroll
    for (int o = 16; o; o >>= 1) {
        s_lq += __shfl_xor_sync(0xffffffffu, s_lq, o);
        s_plp += __shfl_xor_sync(0xffffffffu, s_plp, o);
        s_kl += __shfl_xor_sync(0xffffffffu, s_kl, o);
    }
    __shared__ float r0[8], r1[8], r2[8];
    __shared__ float sh_c;
    if (lane == 0) { r0[w] = s_lq; r1[w] = s_plp; r2[w] = s_kl; }
    __syncthreads();
    if (t == 0) {
        float t0 = 0.f, t1 = 0.f, t2 = 0.f;
#pragma unroll
        for (int i = 0; i < 8; i++) { t0 += r0[i]; t1 += r1[i]; t2 += r2[i]; }
        float c = t0 * (1.0f / (float)DDIM);
        g_c[r] = c;
        g_pe[r] = t1;
        g_kldiv[r] = t2 * (1.0f / (float)DDIM);
        sh_c = c;
    }
    __syncthreads();
    const float c = sh_c;

    uint32_t packA = 0, packB = 0;
#pragma unroll
    for (int i = 0; i < 4; i++) {
        uint32_t fa = __nv_cvt_float_to_fp8(lq[i] - c, __NV_SATFINITE, __NV_E4M3);
        uint32_t fb = __nv_cvt_float_to_fp8(pv[i] * PSCALE, __NV_SATFINITE, __NV_E4M3);
        packA |= fa << (i * 8);
        packB |= fb << (i * 8);
    }
    // thread t covers k-elements [4t, 4t+4) of row r (1 byte each)
    const int kTile = t >> 5;           // 128 elements per tile
    const int atom = (t >> 2) & 7;      // 16B atom within the 128B row
    const int slot = t & 3;             // 4B slot within atom
    const int swA = atom ^ (r & 7);
    size_t aByte = (size_t)((r >> 7) * KTILES + kTile) * A_STAGE_BYTES +
                   (size_t)(r & 127) * 128 + (swA << 4) + slot * 4;
    g_aT[aByte >> 2] = packA;
    size_t bByte = (size_t)((r >> 8) * KTILES + kTile) * B_STAGE_BYTES +
                   (size_t)(r & 255) * 128 + (swA << 4) + slot * 4;
    g_bT[bByte >> 2] = packB;
}

// ============================================================
// Kernel 2: fp8 mma.sync GEMM (128x256 per CTA, 512 thr) + bulk-copy
// pipeline + fused labels epilogue.
//   crossS[i,j] = sum_d lqc[i,d] * (p[j,d]*256)
//   kl_dis[i,j] = (pe[j] - c[i] - crossS/256) / D
// ============================================================
__global__ void __launch_bounds__(512, 1) gemm_kernel(const float* __restrict__ labels) {
    extern __shared__ __align__(1024) char smem[];
    const uint32_t sb = (uint32_t)__cvta_generic_to_shared(smem);
    const int tid = threadIdx.x, wid = tid >> 5, lane = tid & 31;
    const int nb = blockIdx.x, mb = blockIdx.y;
    const int warpM = wid & 1, warpN = wid >> 1;  // 2 x 8 warp grid, 64x32 tiles

    float* pe_s = (float*)(smem + 1024);  // 256 floats, lives in TILE0 region

    if (tid == 0) {
#pragma unroll
        for (int s = 0; s < STAGES; s++) {
            mbar_init(sb + s * 16, 1);       // full[s]: producer expect_tx
            mbar_init(sb + s * 16 + 8, 16);  // empty[s]: one arrive per warp
        }
    }
    if (tid < 256) pe_s[tid] = g_pe[nb * BN + tid];
    __syncthreads();

    const char* gA = (const char*)g_aT + (size_t)(mb * KTILES) * A_STAGE_BYTES;
    const char* gB = (const char*)g_bT + (size_t)(nb * KTILES) * B_STAGE_BYTES;

    // prefill all stages
    if (tid == 0) {
#pragma unroll
        for (int s = 0; s < STAGES; s++) {
            uint32_t full = sb + s * 16;
            uint32_t dst = sb + TILE0 + s * STAGE_BYTES;
            mbar_expect_tx(full, STAGE_BYTES);
            bulk_g2s(dst, gA + (size_t)s * A_STAGE_BYTES, A_STAGE_BYTES, full);
            bulk_g2s(dst + A_STAGE_BYTES, gB + (size_t)s * B_STAGE_BYTES, B_STAGE_BYTES, full);
        }
    }

    float acc[4][4][4];
#pragma unroll
    for (int a = 0; a < 4; a++)
#pragma unroll
        for (int b = 0; b < 4; b++)
#pragma unroll
            for (int cc = 0; cc < 4; cc++) acc[a][b][cc] = 0.f;

    const int m = lane >> 3;  // ldmatrix sub-matrix id
    const int l8 = lane & 7;

    for (int kt = 0; kt < KTILES; kt++) {
        const int s = kt & (STAGES - 1);
        const uint32_t ph = (kt >> 2) & 1;
        const uint32_t full = sb + s * 16;
        const uint32_t empty = sb + s * 16 + 8;
        const uint32_t bA = sb + TILE0 + s * STAGE_BYTES;
        const uint32_t bB = bA + A_STAGE_BYTES;

        mbar_wait(full, ph);

#pragma unroll
        for (int kh = 0; kh < 4; kh++) {  // K=32 fp8 elements (2 atoms) per step
            uint32_t a[4][4];
            uint32_t b[4][2];
#pragma unroll
            for (int mi = 0; mi < 4; mi++) {
                int row = warpM * 64 + mi * 16 + ((m & 1) << 3) + l8;
                int atom = kh * 2 + (m >> 1);
                ldm4(a[mi][0], a[mi][1], a[mi][2], a[mi][3], bA + swz(row, atom));
            }
#pragma unroll
            for (int np = 0; np < 2; np++) {
                int row = warpN * 32 + np * 16 + ((m >> 1) << 3) + l8;
                int atom = kh * 2 + (m & 1);
                uint32_t r0, r1, r2, r3;
                ldm4(r0, r1, r2, r3, bB + swz(row, atom));
                b[np * 2][0] = r0; b[np * 2][1] = r1;
                b[np * 2 + 1][0] = r2; b[np * 2 + 1][1] = r3;
            }
#pragma unroll
            for (int mi = 0; mi < 4; mi++)
#pragma unroll
                for (int ni = 0; ni < 4; ni++) mma16832(acc[mi][ni], a[mi], b[ni]);
        }

        if (lane == 0) mbar_arrive(empty);
        if (tid == 0 && kt + STAGES < KTILES) {
            mbar_wait(empty, ph);  // all 16 warps done reading stage s
            mbar_expect_tx(full, STAGE_BYTES);
            bulk_g2s(bA, gA + (size_t)(kt + STAGES) * A_STAGE_BYTES, A_STAGE_BYTES, full);
            bulk_g2s(bB, gB + (size_t)(kt + STAGES) * B_STAGE_BYTES, B_STAGE_BYTES, full);
        }
    }

    // ---------------- epilogue ----------------
    const float invD = 1.0f / (float)DDIM;
    const int rWarp = mb * BM + warpM * 64;
    const int cWarp = warpN * 32;  // within tile; global col = nb*BN + cWarp
    const int rLane = lane >> 2;
    const int cLane = (lane & 3) << 1;

    float cRow[4][2], pe0[4], pe1[4];
#pragma unroll
    for (int mi = 0; mi < 4; mi++)
#pragma unroll
        for (int rh = 0; rh < 2; rh++)
            cRow[mi][rh] = g_c[rWarp + mi * 16 + rh * 8 + rLane];
#pragma unroll
    for (int ni = 0; ni < 4; ni++) {
        pe0[ni] = pe_s[cWarp + ni * 8 + cLane];
        pe1[ni] = pe_s[cWarp + ni * 8 + cLane + 1];
    }

    float labS[4][2], allS[4][2];
#pragma unroll
    for (int mi = 0; mi < 4; mi++)
#pragma unroll
        for (int rh = 0; rh < 2; rh++) { labS[mi][rh] = 0.f; allS[mi][rh] = 0.f; }

#pragma unroll
    for (int mi = 0; mi < 4; mi++) {
#pragma unroll
        for (int rh = 0; rh < 2; rh++) {
            int r = rWarp + mi * 16 + rh * 8 + rLane;
            const float* lrow = labels + (size_t)r * BDIM + nb * BN;
#pragma unroll
            for (int ni = 0; ni < 4; ni++) {
                float2 lb = *reinterpret_cast<const float2*>(lrow + cWarp + ni * 8 + cLane);
                float v0 =
                    (pe0[ni] - cRow[mi][rh] - acc[mi][ni][rh * 2 + 0] * INV_PSCALE) * invD;
                float v1 =
                    (pe1[ni] - cRow[mi][rh] - acc[mi][ni][rh * 2 + 1] * INV_PSCALE) * invD;
                allS[mi][rh] += v0 + v1;
                labS[mi][rh] += lb.x * v0 + lb.y * v1;
            }
        }
    }

    __syncthreads();  // stage smem dead; reuse for row reduction
    float* eLab = (float*)(smem + TILE0);  // [8][128]
    float* eAll = eLab + 8 * BM;           // [8][128]

#pragma unroll
    for (int mi = 0; mi < 4; mi++)
#pragma unroll
        for (int rh = 0; rh < 2; rh++) {
            float l = labS[mi][rh], a = allS[mi][rh];
            l += __shfl_xor_sync(0xffffffffu, l, 1);
            l += __shfl_xor_sync(0xffffffffu, l, 2);
            a += __shfl_xor_sync(0xffffffffu, a, 1);
            a += __shfl_xor_sync(0xffffffffu, a, 2);
            if ((lane & 3) == 0) {
                int lr = warpM * 64 + mi * 16 + rh * 8 + rLane;
                eLab[warpN * BM + lr] = l;
                eAll[warpN * BM + lr] = a;
            }
        }
    __syncthreads();
    if (tid < BM) {
        float l = 0.f, a = 0.f;
#pragma unroll
        for (int wn = 0; wn < 8; wn++) {
            l += eLab[wn * BM + tid];
            a += eAll[wn * BM + tid];
        }
        g_partLab[(size_t)nb * BDIM + mb * BM + tid] = l;
        g_partAll[(size_t)nb * BDIM + mb * BM + tid] = a;
    }
}

// ============================================================
// Kernel 3: final reduction (16 CTAs + last-block finish)
// ============================================================
__global__ void __launch_bounds__(256) final_kernel(float* __restrict__ out) {
    const int b = blockIdx.x, t = threadIdx.x;
    const int lane = t & 31, w = t >> 5;
    const int i = b * 256 + t;
    float lab = 0.f, all = 0.f;
#pragma unroll
    for (int cb = 0; cb < NT; cb++) {
        lab += g_partLab[(size_t)cb * BDIM + i];
        all += g_partAll[(size_t)cb * BDIM + i];
    }
    float s = (g_kldiv[i] + lab) / (all - lab);
#pragma unroll
    for (int o = 16; o; o >>= 1) s += __shfl_xor_sync(0xffffffffu, s, o);
    __shared__ float wr[8];
    if (lane == 0) wr[w] = s;
    __syncthreads();
    if (t == 0) {
        float v = 0.f;
#pragma unroll
        for (int k = 0; k < 8; k++) v += wr[k];
        g_rowsum[b] = v;
        __threadfence();
        int ticket = atomicAdd(&g_cnt, 1);
        if (ticket == 15) {
            float tot = 0.f;
#pragma unroll
            for (int k = 0; k < 16; k++) tot += g_rowsum[k];
            out[0] = tot;
            g_cnt = 0;  // reset for next graph replay
        }
    }
}

extern "C" void kernel_launch(void* const* d_in, const int* in_sizes, int n_in,
                              void* d_out, int out_size) {
    const float* q = (const float*)d_in[0];
    const float* p = (const float*)d_in[1];
    const float* labels = (const float*)d_in[2];
    (void)in_sizes; (void)n_in; (void)out_size;

    cudaFuncSetAttribute(gemm_kernel, cudaFuncAttributeMaxDynamicSharedMemorySize, GEMM_SMEM);

    prep_kernel<<<BDIM, 256>>>(q, p);
    dim3 grid(NT, MT);
    gemm_kernel<<<grid, 512, GEMM_SMEM>>>(labels);
    final_kernel<<<16, 256>>>((float*)d_out);
}

// round 6
// speedup vs baseline: 1.2312x; 1.2312x over previous
#include <cuda_runtime.h>
#include <cuda_bf16.h>
#include <cstdint>

#define BDIM 4096
#define DDIM 1024
#define BM 128
#define BN 256
#define BK 64
#define KTILES 16           /* 1024 / 64 */
#define MT 32               /* 4096 / 128 */
#define NT 16               /* 4096 / 256 */
#define STAGES 4
#define A_STAGE_BYTES 16384 /* 128 rows x 128B */
#define B_STAGE_BYTES 32768 /* 256 rows x 128B */
#define STAGE_BYTES (A_STAGE_BYTES + B_STAGE_BYTES)
#define TILE0 3072
#define GEMM_SMEM (TILE0 + STAGES * STAGE_BYTES) /* 199680 */

// ---- scratch (static device globals; no runtime allocation) ----
__device__ float g_pe[BDIM];
__device__ float g_c[BDIM];
__device__ float g_kldiv[BDIM];
// tiled + swizzled operand storage, written by prep:
//  A: [mTile(32)][kTile(16)] tiles of 128 rows x 128 bytes (bf16 centered log q)
//  B: [nTile(16)][kTile(16)] tiles of 256 rows x 128 bytes (bf16 p)
__device__ __align__(1024) unsigned long long g_aT[(size_t)BDIM * DDIM / 4];
__device__ __align__(1024) unsigned long long g_bT[(size_t)BDIM * DDIM / 4];
__device__ float g_partLab[(size_t)NT * BDIM];
__device__ float g_partAll[(size_t)NT * BDIM];
__device__ float g_rowsum[16];
__device__ int g_cnt;

// ============================================================
// PTX helpers (non-"a" features only: mbarrier, bulk copy, mma.sync)
// ============================================================
__device__ __forceinline__ void mbar_init(uint32_t mbar, uint32_t cnt) {
    asm volatile("mbarrier.init.shared.b64 [%0], %1;" ::"r"(mbar), "r"(cnt) : "memory");
}
__device__ __forceinline__ void mbar_expect_tx(uint32_t mbar, uint32_t bytes) {
    asm volatile("mbarrier.arrive.expect_tx.shared.b64 _, [%0], %1;" ::"r"(mbar), "r"(bytes)
                 : "memory");
}
__device__ __forceinline__ void mbar_arrive(uint32_t mbar) {
    asm volatile("mbarrier.arrive.shared.b64 _, [%0];" ::"r"(mbar) : "memory");
}
__device__ __forceinline__ void mbar_wait(uint32_t mbar, uint32_t parity) {
    uint32_t done;
    asm volatile(
        "{\n\t.reg .pred p;\n\t"
        "mbarrier.try_wait.parity.acquire.cta.shared::cta.b64 p, [%1], %2;\n\t"
        "selp.b32 %0, 1, 0, p;\n\t}"
        : "=r"(done)
        : "r"(mbar), "r"(parity)
        : "memory");
    if (!done) {
        asm volatile(
            "{\n\t.reg .pred P1;\n\t"
            "WAIT_LOOP_%=:\n\t"
            "mbarrier.try_wait.parity.acquire.cta.shared::cta.b64 P1, [%0], %1, 0x989680;\n\t"
            "@P1 bra.uni WAIT_DONE_%=;\n\t"
            "bra.uni WAIT_LOOP_%=;\n\t"
            "WAIT_DONE_%=:\n\t}" ::"r"(mbar),
            "r"(parity)
            : "memory");
    }
}
__device__ __forceinline__ void bulk_g2s(uint32_t dst, const void* src, uint32_t bytes,
                                         uint32_t mbar) {
    asm volatile(
        "cp.async.bulk.shared::cluster.global.mbarrier::complete_tx::bytes [%0], [%1], %2, [%3];"
        ::"r"(dst), "l"(src), "r"(bytes), "r"(mbar)
        : "memory");
}
__device__ __forceinline__ void mma16816(float* d, const uint32_t* a, const uint32_t* b) {
    asm volatile(
        "mma.sync.aligned.m16n8k16.row.col.f32.bf16.bf16.f32 "
        "{%0,%1,%2,%3}, {%4,%5,%6,%7}, {%8,%9}, {%0,%1,%2,%3};\n"
        : "+f"(d[0]), "+f"(d[1]), "+f"(d[2]), "+f"(d[3])
        : "r"(a[0]), "r"(a[1]), "r"(a[2]), "r"(a[3]), "r"(b[0]), "r"(b[1]));
}
__device__ __forceinline__ void ldm4(uint32_t& r0, uint32_t& r1, uint32_t& r2, uint32_t& r3,
                                     uint32_t addr) {
    asm volatile("ldmatrix.sync.aligned.m8n8.x4.shared.b16 {%0,%1,%2,%3}, [%4];\n"
                 : "=r"(r0), "=r"(r1), "=r"(r2), "=r"(r3)
                 : "r"(addr));
}
__device__ __forceinline__ void prefetchL2(const void* p) {
    asm volatile("prefetch.global.L2 [%0];" ::"l"(p));
}
// swizzled smem byte offset inside one [rows x 128B] tile (atom=16B, 8 atoms/row):
__device__ __forceinline__ uint32_t swz(int row, int atom) {
    return (uint32_t)(row * 128 + ((atom ^ (row & 7)) << 4));
}

// ============================================================
// Kernel 1: per-row preprocess + tiled/swizzled bf16 operand store
//   pe[i] = sum p log p ; c[i] = mean log q ; kldiv[i] = mean p(lp-lq)
//   A tiles: bf16(log q - c)   B tiles: bf16(p)
// ============================================================
__global__ void __launch_bounds__(256) prep_kernel(const float* __restrict__ q,
                                                   const float* __restrict__ p) {
    const int r = blockIdx.x;
    const int t = threadIdx.x;
    const int lane = t & 31, w = t >> 5;

    float4 q4 = ((const float4*)(q + (size_t)r * DDIM))[t];
    float4 p4 = ((const float4*)(p + (size_t)r * DDIM))[t];
    float lq[4] = {__logf(q4.x), __logf(q4.y), __logf(q4.z), __logf(q4.w)};
    float lp[4] = {__logf(p4.x), __logf(p4.y), __logf(p4.z), __logf(p4.w)};
    float pv[4] = {p4.x, p4.y, p4.z, p4.w};

    float s_lq = (lq[0] + lq[1]) + (lq[2] + lq[3]);
    float s_plp = 0.f, s_kl = 0.f;
#pragma unroll
    for (int i = 0; i < 4; i++) {
        s_plp += pv[i] * lp[i];
        s_kl += pv[i] * (lp[i] - lq[i]);
    }
#pragma unroll
    for (int o = 16; o; o >>= 1) {
        s_lq += __shfl_xor_sync(0xffffffffu, s_lq, o);
        s_plp += __shfl_xor_sync(0xffffffffu, s_plp, o);
        s_kl += __shfl_xor_sync(0xffffffffu, s_kl, o);
    }
    __shared__ float r0[8], r1[8], r2[8];
    __shared__ float sh_c;
    if (lane == 0) { r0[w] = s_lq; r1[w] = s_plp; r2[w] = s_kl; }
    __syncthreads();
    if (t == 0) {
        float t0 = 0.f, t1 = 0.f, t2 = 0.f;
#pragma unroll
        for (int i = 0; i < 8; i++) { t0 += r0[i]; t1 += r1[i]; t2 += r2[i]; }
        float c = t0 * (1.0f / (float)DDIM);
        g_c[r] = c;
        g_pe[r] = t1;
        g_kldiv[r] = t2 * (1.0f / (float)DDIM);
        sh_c = c;
    }
    __syncthreads();
    const float c = sh_c;

    union {
        unsigned long long u;
        __nv_bfloat16 h[4];
    } ua, ub;
#pragma unroll
    for (int i = 0; i < 4; i++) {
        ua.h[i] = __float2bfloat16(lq[i] - c);
        ub.h[i] = __float2bfloat16(pv[i]);
    }
    // thread t covers k-elements [4t, 4t+4) of row r
    const int kTile = t >> 4;
    const int atom = (t >> 1) & 7;
    const int halfa = t & 1;
    const int swA = atom ^ (r & 7);
    size_t aByte = (size_t)((r >> 7) * KTILES + kTile) * A_STAGE_BYTES +
                   (size_t)(r & 127) * 128 + (swA << 4) + halfa * 8;
    g_aT[aByte >> 3] = ua.u;
    size_t bByte = (size_t)((r >> 8) * KTILES + kTile) * B_STAGE_BYTES +
                   (size_t)(r & 255) * 128 + (swA << 4) + halfa * 8;
    g_bT[bByte >> 3] = ub.u;
}

// ============================================================
// Kernel 2: bf16 mma.sync GEMM (128x256 per CTA, 512 thr) + bulk-copy
// pipeline + fused labels epilogue (labels L2-prefetched at start).
//   cross_c[i,j] = sum_d lqc[i,d]*p[j,d]
//   kl_dis[i,j]  = (pe[j] - c[i] - cross_c[i,j]) / D
// ============================================================
__global__ void __launch_bounds__(512, 1) gemm_kernel(const float* __restrict__ labels) {
    extern __shared__ __align__(1024) char smem[];
    const uint32_t sb = (uint32_t)__cvta_generic_to_shared(smem);
    const int tid = threadIdx.x, wid = tid >> 5, lane = tid & 31;
    const int nb = blockIdx.x, mb = blockIdx.y;
    const int warpM = wid & 1, warpN = wid >> 1;  // 2 x 8 warp grid, 64x32 tiles

    float* pe_s = (float*)(smem + 1024);  // 256 floats, lives in TILE0 region

    if (tid == 0) {
#pragma unroll
        for (int s = 0; s < STAGES; s++) {
            mbar_init(sb + s * 16, 1);       // full[s]: producer expect_tx
            mbar_init(sb + s * 16 + 8, 16);  // empty[s]: one arrive per warp
        }
    }
    if (tid < 256) pe_s[tid] = g_pe[nb * BN + tid];
    __syncthreads();

    const char* gA = (const char*)g_aT + (size_t)(mb * KTILES) * A_STAGE_BYTES;
    const char* gB = (const char*)g_bT + (size_t)(nb * KTILES) * B_STAGE_BYTES;

    // prefill all stages
    if (tid == 0) {
#pragma unroll
        for (int s = 0; s < STAGES; s++) {
            uint32_t full = sb + s * 16;
            uint32_t dst = sb + TILE0 + s * STAGE_BYTES;
            mbar_expect_tx(full, STAGE_BYTES);
            bulk_g2s(dst, gA + (size_t)s * A_STAGE_BYTES, A_STAGE_BYTES, full);
            bulk_g2s(dst + A_STAGE_BYTES, gB + (size_t)s * B_STAGE_BYTES, B_STAGE_BYTES, full);
        }
    }

    // prefetch this CTA's labels block (128 rows x 1KB) into L2 while MMAs run
    {
        const char* lbase = (const char*)(labels + (size_t)mb * BM * BDIM + nb * BN);
#pragma unroll
        for (int e = 0; e < 2; e++) {
            int l = tid + e * 512;             // line id in [0,1024)
            const char* addr = lbase + (size_t)(l >> 3) * (BDIM * 4) + (l & 7) * 128;
            prefetchL2(addr);
        }
    }

    float acc[4][4][4];
#pragma unroll
    for (int a = 0; a < 4; a++)
#pragma unroll
        for (int b = 0; b < 4; b++)
#pragma unroll
            for (int cc = 0; cc < 4; cc++) acc[a][b][cc] = 0.f;

    const int m = lane >> 3;  // ldmatrix sub-matrix id
    const int l8 = lane & 7;

    for (int kt = 0; kt < KTILES; kt++) {
        const int s = kt & (STAGES - 1);
        const uint32_t ph = (kt >> 2) & 1;
        const uint32_t full = sb + s * 16;
        const uint32_t empty = sb + s * 16 + 8;
        const uint32_t bA = sb + TILE0 + s * STAGE_BYTES;
        const uint32_t bB = bA + A_STAGE_BYTES;

        mbar_wait(full, ph);

#pragma unroll
        for (int kh = 0; kh < 4; kh++) {
            uint32_t a[4][4];
            uint32_t b[4][2];
#pragma unroll
            for (int mi = 0; mi < 4; mi++) {
                int row = warpM * 64 + mi * 16 + ((m & 1) << 3) + l8;
                int atom = kh * 2 + (m >> 1);
                ldm4(a[mi][0], a[mi][1], a[mi][2], a[mi][3], bA + swz(row, atom));
            }
#pragma unroll
            for (int np = 0; np < 2; np++) {
                int row = warpN * 32 + np * 16 + ((m >> 1) << 3) + l8;
                int atom = kh * 2 + (m & 1);
                uint32_t r0, r1, r2, r3;
                ldm4(r0, r1, r2, r3, bB + swz(row, atom));
                b[np * 2][0] = r0; b[np * 2][1] = r1;
                b[np * 2 + 1][0] = r2; b[np * 2 + 1][1] = r3;
            }
#pragma unroll
            for (int mi = 0; mi < 4; mi++)
#pragma unroll
                for (int ni = 0; ni < 4; ni++) mma16816(acc[mi][ni], a[mi], b[ni]);
        }

        if (lane == 0) mbar_arrive(empty);
        if (tid == 0 && kt + STAGES < KTILES) {
            mbar_wait(empty, ph);  // all 16 warps done reading stage s
            mbar_expect_tx(full, STAGE_BYTES);
            bulk_g2s(bA, gA + (size_t)(kt + STAGES) * A_STAGE_BYTES, A_STAGE_BYTES, full);
            bulk_g2s(bB, gB + (size_t)(kt + STAGES) * B_STAGE_BYTES, B_STAGE_BYTES, full);
        }
    }

    // ---------------- epilogue ----------------
    const float invD = 1.0f / (float)DDIM;
    const int rWarp = mb * BM + warpM * 64;
    const int cWarp = warpN * 32;  // within tile; global col = nb*BN + cWarp
    const int rLane = lane >> 2;
    const int cLane = (lane & 3) << 1;

    float cRow[4][2], pe0[4], pe1[4];
#pragma unroll
    for (int mi = 0; mi < 4; mi++)
#pragma unroll
        for (int rh = 0; rh < 2; rh++)
            cRow[mi][rh] = g_c[rWarp + mi * 16 + rh * 8 + rLane];
#pragma unroll
    for (int ni = 0; ni < 4; ni++) {
        pe0[ni] = pe_s[cWarp + ni * 8 + cLane];
        pe1[ni] = pe_s[cWarp + ni * 8 + cLane + 1];
    }

    float labS[4][2], allS[4][2];
#pragma unroll
    for (int mi = 0; mi < 4; mi++)
#pragma unroll
        for (int rh = 0; rh < 2; rh++) { labS[mi][rh] = 0.f; allS[mi][rh] = 0.f; }

#pragma unroll
    for (int mi = 0; mi < 4; mi++) {
#pragma unroll
        for (int rh = 0; rh < 2; rh++) {
            int r = rWarp + mi * 16 + rh * 8 + rLane;
            const float* lrow = labels + (size_t)r * BDIM + nb * BN;
#pragma unroll
            for (int ni = 0; ni < 4; ni++) {
                float2 lb = *reinterpret_cast<const float2*>(lrow + cWarp + ni * 8 + cLane);
                float v0 = (pe0[ni] - cRow[mi][rh] - acc[mi][ni][rh * 2 + 0]) * invD;
                float v1 = (pe1[ni] - cRow[mi][rh] - acc[mi][ni][rh * 2 + 1]) * invD;
                allS[mi][rh] += v0 + v1;
                labS[mi][rh] += lb.x * v0 + lb.y * v1;
            }
        }
    }

    __syncthreads();  // stage smem dead; reuse for row reduction
    float* eLab = (float*)(smem + TILE0);  // [8][128]
    float* eAll = eLab + 8 * BM;           // [8][128]

#pragma unroll
    for (int mi = 0; mi < 4; mi++)
#pragma unroll
        for (int rh = 0; rh < 2; rh++) {
            float l = labS[mi][rh], a = allS[mi][rh];
            l += __shfl_xor_sync(0xffffffffu, l, 1);
            l += __shfl_xor_sync(0xffffffffu, l, 2);
            a += __shfl_xor_sync(0xffffffffu, a, 1);
            a += __shfl_xor_sync(0xffffffffu, a, 2);
            if ((lane & 3) == 0) {
                int lr = warpM * 64 + mi * 16 + rh * 8 + rLane;
                eLab[warpN * BM + lr] = l;
                eAll[warpN * BM + lr] = a;
            }
        }
    __syncthreads();
    if (tid < BM) {
        float l = 0.f, a = 0.f;
#pragma unroll
        for (int wn = 0; wn < 8; wn++) {
            l += eLab[wn * BM + tid];
            a += eAll[wn * BM + tid];
        }
        g_partLab[(size_t)nb * BDIM + mb * BM + tid] = l;
        g_partAll[(size_t)nb * BDIM + mb * BM + tid] = a;
    }
}

// ============================================================
// Kernel 3: final reduction (16 CTAs + last-block finish)
// ============================================================
__global__ void __launch_bounds__(256) final_kernel(float* __restrict__ out) {
    const int b = blockIdx.x, t = threadIdx.x;
    const int lane = t & 31, w = t >> 5;
    const int i = b * 256 + t;
    float lab = 0.f, all = 0.f;
#pragma unroll
    for (int cb = 0; cb < NT; cb++) {
        lab += g_partLab[(size_t)cb * BDIM + i];
        all += g_partAll[(size_t)cb * BDIM + i];
    }
    float s = (g_kldiv[i] + lab) / (all - lab);
#pragma unroll
    for (int o = 16; o; o >>= 1) s += __shfl_xor_sync(0xffffffffu, s, o);
    __shared__ float wr[8];
    if (lane == 0) wr[w] = s;
    __syncthreads();
    if (t == 0) {
        float v = 0.f;
#pragma unroll
        for (int k = 0; k < 8; k++) v += wr[k];
        g_rowsum[b] = v;
        __threadfence();
        int ticket = atomicAdd(&g_cnt, 1);
        if (ticket == 15) {
            float tot = 0.f;
#pragma unroll
            for (int k = 0; k < 16; k++) tot += g_rowsum[k];
            out[0] = tot;
            g_cnt = 0;  // reset for next graph replay
        }
    }
}

extern "C" void kernel_launch(void* const* d_in, const int* in_sizes, int n_in,
                              void* d_out, int out_size) {
    const float* q = (const float*)d_in[0];
    const float* p = (const float*)d_in[1];
    const float* labels = (const float*)d_in[2];
    (void)in_sizes; (void)n_in; (void)out_size;

    cudaFuncSetAttribute(gemm_kernel, cudaFuncAttributeMaxDynamicSharedMemorySize, GEMM_SMEM);

    prep_kernel<<<BDIM, 256>>>(q, p);
    dim3 grid(NT, MT);
    gemm_kernel<<<grid, 512, GEMM_SMEM>>>(labels);
    final_kernel<<<16, 256>>>((float*)d_out);
}